// round 1
// baseline (speedup 1.0000x reference)
#include <cuda_runtime.h>

// Problem constants (from reference setup_inputs):
// B=32, S=12, F=128, H=64, K=8, C=64, N=512
#define B_   32
#define S_   12
#define F_   128
#define H_   64
#define K_   8
#define C_   64
#define N_   512
#define KH_  (K_*H_)        // 512
#define WFC_ (N_*C_)        // 32768 columns of Wf per row
#define NCHUNK_ 8           // split n=512 into 8 chunks of 64

// Scratch (no device mallocs allowed):
__device__ float g_Who[B_*C_];              // 2048 floats
__device__ float g_part[C_*NCHUNK_*C_];     // 64*8*64 = 32768 floats

// Kernel 1:
//  blocks [0, 32): per-batch GAT collapse -> g_Who[b, c]
//  blocks [32, 32+512): Wf chunk reduction -> g_part[(c'*8+chunk)*64 + c]
__global__ __launch_bounds__(512) void k1(
    const float* __restrict__ x,        // (B, S, F)
    const float* __restrict__ W_heads,  // (K, F, H)
    const float* __restrict__ W_out,    // (K*H, C)
    const float* __restrict__ Wf)       // (C, N*C)
{
    __shared__ float xs[F_];
    __shared__ float hcat[KH_];
    __shared__ float partial[512];

    const int t   = threadIdx.x;
    const int bid = blockIdx.x;

    if (bid < B_) {
        // ---- Part A: Who[b, :] ----
        const int b = bid;
        if (t < F_) xs[t] = x[(b * S_ + (S_ - 1)) * F_ + t];
        __syncthreads();

        // Wh[k,h]: thread t = k*64 + h, dot over F=128
        const int k = t >> 6;
        const int h = t & 63;
        const float* wp = W_heads + (size_t)(k * F_) * H_ + h;
        float acc = 0.f;
        #pragma unroll 8
        for (int f = 0; f < F_; ++f) acc = fmaf(xs[f], wp[(size_t)f * H_], acc);
        // ELU (att-softmax is exactly uniform -> att@Wh == Wh)
        hcat[t] = acc > 0.f ? acc : expm1f(acc);
        __syncthreads();

        // Who[c] = sum_j hcat[j] * W_out[j*C + c]
        const int c  = t & 63;
        const int j0 = t >> 6;   // 0..7
        float p = 0.f;
        #pragma unroll
        for (int j = j0; j < KH_; j += 8) p = fmaf(hcat[j], W_out[(size_t)j * C_ + c], p);
        partial[t] = p;
        __syncthreads();
        if (t < C_) {
            float s = 0.f;
            #pragma unroll
            for (int g = 0; g < 8; ++g) s += partial[g * 64 + t];
            g_Who[b * C_ + t] = s;
        }
    } else {
        // ---- Part B: Wf partial reduction (the only DRAM-heavy work) ----
        const int bid2  = bid - B_;      // 0..511
        const int cp    = bid2 >> 3;     // output channel c' 0..63
        const int chunk = bid2 & 7;      // n-chunk 0..7 (64 n's each)
        const int c     = t & 63;
        const int nl0   = t >> 6;        // 0..7
        const float* wrow = Wf + (size_t)cp * WFC_ + (size_t)(chunk * 64) * C_;
        // each iteration: 512 threads read 2KB contiguous; unroll -> MLP 8
        float p = 0.f;
        #pragma unroll
        for (int nl = nl0; nl < 64; nl += 8) p += wrow[(size_t)nl * C_ + c];
        partial[t] = p;
        __syncthreads();
        if (t < C_) {
            float s = 0.f;
            #pragma unroll
            for (int g = 0; g < 8; ++g) s += partial[g * 64 + t];
            g_part[(size_t)bid2 * C_ + t] = s;
        }
    }
}

// Kernel 2: one block per c'. Fold 8 chunk partials -> WfSum[c', :] in smem,
// then out[b, c'] = bf[c'] + sum_c Who[b,c] * WfSum[c', c].
__global__ __launch_bounds__(256) void k2(
    const float* __restrict__ bf,
    float* __restrict__ out)
{
    __shared__ float tmp[512];
    __shared__ float wfs[C_];
    const int cp = blockIdx.x;
    const int t  = threadIdx.x;

    tmp[t]       = g_part[cp * 512 + t];
    tmp[t + 256] = g_part[cp * 512 + t + 256];
    __syncthreads();
    if (t < C_) {
        float s = 0.f;
        #pragma unroll
        for (int g = 0; g < 8; ++g) s += tmp[g * 64 + t];
        wfs[t] = s;
    }
    __syncthreads();
    if (t < B_) {
        const int b = t;
        float acc = bf[cp];
        #pragma unroll 8
        for (int c = 0; c < C_; ++c) acc = fmaf(g_Who[b * C_ + c], wfs[c], acc);
        out[b * C_ + cp] = acc;
    }
}

extern "C" void kernel_launch(void* const* d_in, const int* in_sizes, int n_in,
                              void* d_out, int out_size)
{
    const float* x       = (const float*)d_in[0]; // (32,12,128)
    const float* W_heads = (const float*)d_in[1]; // (8,128,64)
    // d_in[2], d_in[3]: a1_heads/a2_heads — provably unused (uniform softmax)
    const float* W_out   = (const float*)d_in[4]; // (512,64)
    // d_in[5], d_in[6]: a1_out/a2_out — unused
    const float* Wf      = (const float*)d_in[7]; // (64, 32768)
    const float* bf      = (const float*)d_in[8]; // (64,)
    float* out = (float*)d_out;                   // (32,64) = 2048

    k1<<<B_ + C_ * NCHUNK_, 512>>>(x, W_heads, W_out, Wf);
    k2<<<C_, 256>>>(bf, out);
}

// round 2
// speedup vs baseline: 1.2196x; 1.2196x over previous
#include <cuda_runtime.h>

// Problem constants: B=32, S=12, F=128, H=64, K=8, C=64, N=512
#define B_   32
#define S_   12
#define F_   128
#define H_   64
#define K_   8
#define C_   64
#define N_   512
#define KH_  (K_*H_)        // 512
#define WFC_ (N_*C_)        // 32768 floats per Wf row

// Scratch (no device mallocs allowed):
__device__ float g_Who[B_*C_];     // 2048 floats
__device__ float g_wfs[C_*C_];     // WfSum[c'][c], 4096 floats

// Kernel 1, 96 blocks x 1024 threads, one wave:
//  blocks [0,64):  WfSum[c',:] — each block streams one full 128KB Wf row
//  blocks [64,96): Who[b,:]    — GAT collapse (uniform softmax => att@Wh == Wh)
__global__ __launch_bounds__(1024) void k1(
    const float* __restrict__ x,        // (B, S, F)
    const float* __restrict__ W_heads,  // (K, F, H)
    const float* __restrict__ W_out,    // (K*H, C)
    const float* __restrict__ Wf)       // (C, N*C)
{
    const int t   = threadIdx.x;
    const int bid = blockIdx.x;

    if (bid < C_) {
        // ---- Wf row reduction: the only DRAM-heavy work (8.4 MB total) ----
        __shared__ float4 part4[1024];          // 16 KB
        const int cp = bid;
        const int c4 = t & 15;                  // which float4 within a 64-float n-row
        const int n0 = t >> 4;                  // 0..63
        const float4* __restrict__ row = (const float4*)(Wf + (size_t)cp * WFC_);
        float4 s = make_float4(0.f, 0.f, 0.f, 0.f);
        // 8 fully-independent float4 loads per thread (128 B in flight)
        #pragma unroll
        for (int i = 0; i < 8; ++i) {
            float4 v = row[(size_t)(n0 + i * 64) * 16 + c4];
            s.x += v.x; s.y += v.y; s.z += v.z; s.w += v.w;
        }
        part4[t] = s;
        __syncthreads();
        if (t < C_) {
            // float view: part_f[n0*64 + c]; 64 threads read consecutive -> no conflict
            const float* pf = (const float*)part4;
            float acc = 0.f;
            #pragma unroll
            for (int n0i = 0; n0i < 64; ++n0i) acc += pf[n0i * 64 + t];
            g_wfs[cp * C_ + t] = acc;
        }
    } else {
        // ---- Who[b,:] ----
        __shared__ float xs[F_];
        __shared__ float ws[1024];
        __shared__ float hcat[KH_];
        const int b = bid - C_;
        if (t < F_) xs[t] = x[(b * S_ + (S_ - 1)) * F_ + t];
        __syncthreads();

        // Wh[k,h]: output idx o = t&511, each computed by 2 threads (half of F each)
        {
            const int o    = t & 511;
            const int half = t >> 9;          // 0 or 1
            const int k    = o >> 6;
            const int h    = o & 63;
            const float* wp = W_heads + ((size_t)k * F_ + half * 64) * H_ + h;
            const float* xp = xs + half * 64;
            float acc = 0.f;
            #pragma unroll 8
            for (int f = 0; f < 64; ++f) acc = fmaf(xp[f], wp[(size_t)f * H_], acc);
            ws[t] = acc;
        }
        __syncthreads();
        if (t < KH_) {
            float v = ws[t] + ws[t + 512];
            hcat[t] = v > 0.f ? v : expm1f(v);   // ELU
        }
        __syncthreads();

        // Who[c] = sum_j hcat[j] * W_out[j*C + c], j split 16 ways
        {
            const int c  = t & 63;
            const int j0 = t >> 6;               // 0..15
            float p = 0.f;
            #pragma unroll
            for (int j = j0; j < KH_; j += 16) p = fmaf(hcat[j], W_out[(size_t)j * C_ + c], p);
            ws[t] = p;
        }
        __syncthreads();
        if (t < C_) {
            float s2 = 0.f;
            #pragma unroll
            for (int g = 0; g < 16; ++g) s2 += ws[g * 64 + t];
            g_Who[b * C_ + t] = s2;
        }
    }
}

// Kernel 2: 2 blocks x 1024 threads. Stage Who (16 rows) + full WfSum into smem,
// then out[b,c'] = bf[c'] + sum_c Who[b,c] * WfSum[c',c]. One output per thread.
__global__ __launch_bounds__(1024) void k2(
    const float* __restrict__ bf,
    float* __restrict__ out)
{
    __shared__ float wfs_s[C_ * 65];     // padded rows: bank-conflict-free
    __shared__ float who_s[16 * C_];
    const int t = threadIdx.x;

    // load WfSum (4096 floats) with row padding
    #pragma unroll
    for (int i = t; i < C_ * C_; i += 1024) {
        wfs_s[(i >> 6) * 65 + (i & 63)] = g_wfs[i];
    }
    // load this block's 16 Who rows (1024 floats)
    who_s[t] = g_Who[blockIdx.x * 16 * C_ + t];
    __syncthreads();

    const int bl = t >> 6;       // local batch 0..15 (constant within a warp)
    const int cp = t & 63;
    float acc = bf[cp];
    const float* wr = wfs_s + cp * 65;
    const float* hr = who_s + bl * C_;
    #pragma unroll 8
    for (int c = 0; c < C_; ++c) acc = fmaf(hr[c], wr[c], acc);
    out[(blockIdx.x * 16 + bl) * C_ + cp] = acc;
}

extern "C" void kernel_launch(void* const* d_in, const int* in_sizes, int n_in,
                              void* d_out, int out_size)
{
    const float* x       = (const float*)d_in[0]; // (32,12,128)
    const float* W_heads = (const float*)d_in[1]; // (8,128,64)
    // d_in[2], d_in[3]: a1_heads/a2_heads — unused (softmax over identical rows is uniform)
    const float* W_out   = (const float*)d_in[4]; // (512,64)
    // d_in[5], d_in[6]: a1_out/a2_out — unused
    const float* Wf      = (const float*)d_in[7]; // (64, 32768)
    const float* bf      = (const float*)d_in[8]; // (64,)
    float* out = (float*)d_out;                   // (32,64)

    k1<<<C_ + B_, 1024>>>(x, W_heads, W_out, Wf);
    k2<<<2, 1024>>>(bf, out);
}